// round 1
// baseline (speedup 1.0000x reference)
#include <cuda_runtime.h>
#include <math.h>

#define NMAX 65536

// h2 scratch, stored transposed: g_h2t[f * N + row], f in [0,128)
__device__ float g_h2t[128 * NMAX];

__device__ __forceinline__ float swishf(float v) {
    // v * sigmoid(v); stable at both tails with fast intrinsics
    return __fdividef(v, 1.0f + __expf(-v));
}

// ---------------------------------------------------------------------------
// Kernel 1: BN + Dense(48->128)+swish + Dense(128->128)+swish  -> g_h2t
// Also copies xc = x[:,32:64] into out[:,32:64].
// Block: 64 rows, 256 threads (16 row-threads x 4 rows, 16 col-threads x 8 feats)
// ---------------------------------------------------------------------------
__global__ __launch_bounds__(256)
void k_mlp(const float* __restrict__ x, const float* __restrict__ c,
           const float* __restrict__ bn_scale, const float* __restrict__ bn_bias,
           const float* __restrict__ bn_mean, const float* __restrict__ bn_var,
           const float* __restrict__ W0, const float* __restrict__ b0,
           const float* __restrict__ W1, const float* __restrict__ b1,
           float* __restrict__ out, int N)
{
    extern __shared__ float sm[];
    float* W0s = sm;                  // 48*128   = 6144
    float* W1s = W0s + 48 * 128;      // 128*128  = 16384
    float* b0s = W1s + 128 * 128;     // 128
    float* b1s = b0s + 128;           // 128
    float* ab  = b1s + 128;           // 96 (alpha 48, beta 48)
    float* A0s = ab + 96;             // 48*65  (input, transposed, padded)
    float* A1s = A0s + 48 * 65;       // 128*65 (h1, transposed, padded)
    float* A2s = A1s + 128 * 65;      // 128*64 (h2, transposed)

    const int tid  = threadIdx.x;
    const int row0 = blockIdx.x * 64;

    for (int i = tid; i < 48 * 128; i += 256)  W0s[i] = W0[i];
    for (int i = tid; i < 128 * 128; i += 256) W1s[i] = W1[i];
    if (tid < 128) { b0s[tid] = b0[tid]; b1s[tid] = b1[tid]; }
    if (tid < 48) {
        float a = bn_scale[tid] * rsqrtf(bn_var[tid] + 1e-5f);
        ab[tid]      = a;
        ab[48 + tid] = bn_bias[tid] - bn_mean[tid] * a;
    }
    __syncthreads();

    // Load inputs (xc part of x, then c), apply BN, store transposed.
    for (int idx = tid; idx < 64 * 32; idx += 256) {
        int k = idx & 31, r = idx >> 5;
        float v = x[(size_t)(row0 + r) * 64 + 32 + k];
        out[(size_t)(row0 + r) * 64 + 32 + k] = v;     // y[:,32:64] = xc
        A0s[k * 65 + r] = v * ab[k] + ab[48 + k];
    }
    for (int idx = tid; idx < 64 * 16; idx += 256) {
        int k = idx & 15, r = idx >> 4;
        float v = c[(size_t)(row0 + r) * 16 + k];
        int kk = 32 + k;
        A0s[kk * 65 + r] = v * ab[kk] + ab[48 + kk];
    }
    __syncthreads();

    const int rt = tid >> 4, ct = tid & 15;
    const int r0 = rt * 4, f0 = ct * 8;

    // ---- Layer 0: (64x48) @ (48x128) ----
    {
        float acc[4][8];
        #pragma unroll
        for (int i = 0; i < 4; i++)
            #pragma unroll
            for (int q = 0; q < 8; q++) acc[i][q] = 0.0f;

        #pragma unroll 4
        for (int k = 0; k < 48; k++) {
            float a0 = A0s[k * 65 + r0 + 0];
            float a1 = A0s[k * 65 + r0 + 1];
            float a2 = A0s[k * 65 + r0 + 2];
            float a3 = A0s[k * 65 + r0 + 3];
            float4 wA = *(const float4*)&W0s[k * 128 + f0];
            float4 wB = *(const float4*)&W0s[k * 128 + f0 + 4];
            float w[8] = {wA.x, wA.y, wA.z, wA.w, wB.x, wB.y, wB.z, wB.w};
            #pragma unroll
            for (int q = 0; q < 8; q++) {
                acc[0][q] += a0 * w[q];
                acc[1][q] += a1 * w[q];
                acc[2][q] += a2 * w[q];
                acc[3][q] += a3 * w[q];
            }
        }
        #pragma unroll
        for (int q = 0; q < 8; q++) {
            float bb = b0s[f0 + q];
            #pragma unroll
            for (int i = 0; i < 4; i++)
                A1s[(f0 + q) * 65 + (r0 + i)] = swishf(acc[i][q] + bb);
        }
    }
    __syncthreads();

    // ---- Layer 1: (64x128) @ (128x128) ----
    {
        float acc[4][8];
        #pragma unroll
        for (int i = 0; i < 4; i++)
            #pragma unroll
            for (int q = 0; q < 8; q++) acc[i][q] = 0.0f;

        #pragma unroll 4
        for (int k = 0; k < 128; k++) {
            float a0 = A1s[k * 65 + r0 + 0];
            float a1 = A1s[k * 65 + r0 + 1];
            float a2 = A1s[k * 65 + r0 + 2];
            float a3 = A1s[k * 65 + r0 + 3];
            float4 wA = *(const float4*)&W1s[k * 128 + f0];
            float4 wB = *(const float4*)&W1s[k * 128 + f0 + 4];
            float w[8] = {wA.x, wA.y, wA.z, wA.w, wB.x, wB.y, wB.z, wB.w};
            #pragma unroll
            for (int q = 0; q < 8; q++) {
                acc[0][q] += a0 * w[q];
                acc[1][q] += a1 * w[q];
                acc[2][q] += a2 * w[q];
                acc[3][q] += a3 * w[q];
            }
        }
        #pragma unroll
        for (int q = 0; q < 8; q++) {
            float bb = b1s[f0 + q];
            #pragma unroll
            for (int i = 0; i < 4; i++)
                A2s[(f0 + q) * 64 + (r0 + i)] = swishf(acc[i][q] + bb);
        }
    }
    __syncthreads();

    // Coalesced transposed store of h2
    for (int idx = tid; idx < 128 * 64; idx += 256) {
        int f = idx >> 6, r = idx & 63;
        g_h2t[(size_t)f * N + row0 + r] = A2s[idx];
    }
}

// ---------------------------------------------------------------------------
// Kernel 2: per dim j: p = h2 @ W2[:, 47j:47j+47] + b2, then RQS spline.
// Block: 128 rows, 256 threads (16 row-threads x 8 rows, 16 col-threads x 3 cols)
// ---------------------------------------------------------------------------
__global__ __launch_bounds__(256)
void k_spline(const float* __restrict__ x, const float* __restrict__ W2,
              const float* __restrict__ b2, float* __restrict__ out, int N)
{
    extern __shared__ float sm[];
    float* A  = sm;              // 128*128  h2 tile, [k][r]
    float* Wc = A + 128 * 128;   // 128*48   W2 chunk, [k][c] (col 47 padded 0)
    float* ps = Wc + 128 * 48;   // 128*49   p tile, [r][c] (stride 49 -> no bank conflicts)

    const int tid  = threadIdx.x;
    const int row0 = blockIdx.x * 128;

    for (int idx = tid; idx < 128 * 128; idx += 256) {
        int k = idx >> 7, r = idx & 127;
        A[idx] = g_h2t[(size_t)k * N + row0 + r];
    }

    const int rt = tid >> 4, ct = tid & 15;
    const int r0 = rt * 8, c0 = ct * 3;
    float ld = 0.0f;   // log_det accumulator (threads 0..127)
    __syncthreads();

    for (int j = 0; j < 32; j++) {
        // Load W2 chunk for this output dim (also acts as barrier vs. prev spline)
        for (int idx = tid; idx < 128 * 48; idx += 256) {
            int k = idx / 48, cc = idx - k * 48;
            Wc[idx] = (cc < 47) ? W2[(size_t)k * 1504 + j * 47 + cc] : 0.0f;
        }
        __syncthreads();

        // GEMM: 128 rows x 48 cols x 128 k
        float acc[8][3];
        #pragma unroll
        for (int i = 0; i < 8; i++)
            #pragma unroll
            for (int q = 0; q < 3; q++) acc[i][q] = 0.0f;

        #pragma unroll 8
        for (int k = 0; k < 128; k++) {
            float4 aA = *(const float4*)&A[k * 128 + r0];
            float4 aB = *(const float4*)&A[k * 128 + r0 + 4];
            float w0 = Wc[k * 48 + c0 + 0];
            float w1 = Wc[k * 48 + c0 + 1];
            float w2 = Wc[k * 48 + c0 + 2];
            float av[8] = {aA.x, aA.y, aA.z, aA.w, aB.x, aB.y, aB.z, aB.w};
            #pragma unroll
            for (int i = 0; i < 8; i++) {
                acc[i][0] += av[i] * w0;
                acc[i][1] += av[i] * w1;
                acc[i][2] += av[i] * w2;
            }
        }

        // Epilogue: +bias; pre-exponentiate softmax logits (cols 0..31)
        #pragma unroll
        for (int q = 0; q < 3; q++) {
            int cc = c0 + q;
            if (cc < 47) {
                float bb = __ldg(&b2[j * 47 + cc]);
                #pragma unroll
                for (int i = 0; i < 8; i++) {
                    float p = acc[i][q] + bb;
                    ps[(r0 + i) * 49 + cc] = (cc < 32) ? __expf(p) : p;
                }
            }
        }
        __syncthreads();

        // Spline: one thread per row
        if (tid < 128) {
            const float* pr = &ps[tid * 49];
            float tin = __ldg(&x[(size_t)(row0 + tid) * 64 + j]);

            float sW = 0.0f, sH = 0.0f;
            #pragma unroll
            for (int i = 0; i < 16; i++) { sW += pr[i]; sH += pr[16 + i]; }
            float invW = __fdividef(1.0f, sW);
            float invH = __fdividef(1.0f, sH);

            float tc  = fminf(fmaxf(tin, 0.0f), 1.0f);
            bool  inb = (tin >= 0.0f) && (tin <= 1.0f);

            // Inline cumsum + bin search: pick largest i with xk[i] <= tc
            float xk = 0.0f, cy = 0.0f;
            float xk_b = 0.0f, yk_b = 0.0f;
            float dx_b = pr[0] * invW, dy_b = pr[16] * invH;
            int bidx = 0;
            #pragma unroll
            for (int i = 0; i < 16; i++) {
                float dxi = pr[i] * invW;
                float dyi = pr[16 + i] * invH;
                if (xk <= tc) { bidx = i; xk_b = xk; dx_b = dxi; yk_b = cy; dy_b = dyi; }
                xk += dxi; cy += dyi;
            }

            // Only dk[bidx], dk[bidx+1] needed -> 2 softplus total
            float v0 = pr[32 + ((bidx > 0) ? bidx - 1 : 0)];
            float v1 = pr[32 + ((bidx < 15) ? bidx : 14)];
            float sp0 = fmaxf(v0, 0.0f) + __logf(1.0f + __expf(-fabsf(v0)));
            float sp1 = fmaxf(v1, 0.0f) + __logf(1.0f + __expf(-fabsf(v1)));
            float d0 = (bidx == 0)  ? 1.0f : sp0;
            float d1 = (bidx == 15) ? 1.0f : sp1;

            float xi   = __fdividef(tc - xk_b, dx_b);
            float s    = __fdividef(dy_b, dx_b);
            float xi1m = xi * (1.0f - xi);
            float den  = s + (d0 + d1 - 2.0f * s) * xi1m;
            float num  = s * xi * xi + d0 * xi1m;
            float y_in = yk_b + dy_b * __fdividef(num, den);
            float omxi = 1.0f - xi;
            float dnum = d1 * xi * xi + 2.0f * s * xi1m + d0 * omxi * omxi;
            float dydx = __fdividef(s * s * dnum, den * den);

            out[(size_t)(row0 + tid) * 64 + j] = inb ? y_in : tin;
            ld += inb ? __logf(dydx) : 0.0f;
        }
        __syncthreads();
    }

    if (tid < 128)
        out[(size_t)N * 64 + row0 + tid] = ld;
}

// ---------------------------------------------------------------------------
extern "C" void kernel_launch(void* const* d_in, const int* in_sizes, int n_in,
                              void* d_out, int out_size)
{
    const float* x  = (const float*)d_in[0];
    const float* c  = (const float*)d_in[1];
    const float* bs = (const float*)d_in[2];
    const float* bb = (const float*)d_in[3];
    const float* bm = (const float*)d_in[4];
    const float* bv = (const float*)d_in[5];
    const float* W0 = (const float*)d_in[6];
    const float* b0 = (const float*)d_in[7];
    const float* W1 = (const float*)d_in[8];
    const float* b1 = (const float*)d_in[9];
    const float* W2 = (const float*)d_in[10];
    const float* b2 = (const float*)d_in[11];
    float* out = (float*)d_out;

    int N = in_sizes[0] / 64;

    size_t sm1 = (size_t)(48*128 + 128*128 + 128 + 128 + 96 + 48*65 + 128*65 + 128*64) * sizeof(float);
    size_t sm2 = (size_t)(128*128 + 128*48 + 128*49) * sizeof(float);

    cudaFuncSetAttribute(k_mlp,    cudaFuncAttributeMaxDynamicSharedMemorySize, (int)sm1);
    cudaFuncSetAttribute(k_spline, cudaFuncAttributeMaxDynamicSharedMemorySize, (int)sm2);

    k_mlp<<<N / 64, 256, sm1>>>(x, c, bs, bb, bm, bv, W0, b0, W1, b1, out, N);
    k_spline<<<N / 128, 256, sm2>>>(x, W2, b2, out, N);
}

// round 3
// speedup vs baseline: 1.1449x; 1.1449x over previous
#include <cuda_runtime.h>
#include <cuda_bf16.h>
#include <math.h>
#include <stdint.h>

#define NMAX 65536

// h2 scratch as bf16 hi/lo splits, transposed: [f * N + row]
__device__ __nv_bfloat16 g_h2_hi[128 * NMAX];
__device__ __nv_bfloat16 g_h2_lo[128 * NMAX];

__device__ __forceinline__ float swishf(float v) {
    return __fdividef(v, 1.0f + __expf(-v));
}

__device__ __forceinline__ void split_bf16(float v, __nv_bfloat16* h, __nv_bfloat16* l) {
    __nv_bfloat16 hh = __float2bfloat16(v);
    *h = hh;
    *l = __float2bfloat16(v - __bfloat162float(hh));
}

__device__ __forceinline__ void mma16816(float* c,
                                         uint32_t a0, uint32_t a1, uint32_t a2, uint32_t a3,
                                         uint32_t b0, uint32_t b1) {
    asm volatile(
        "mma.sync.aligned.m16n8k16.row.col.f32.bf16.bf16.f32 "
        "{%0,%1,%2,%3}, {%4,%5,%6,%7}, {%8,%9}, {%0,%1,%2,%3};"
        : "+f"(c[0]), "+f"(c[1]), "+f"(c[2]), "+f"(c[3])
        : "r"(a0), "r"(a1), "r"(a2), "r"(a3), "r"(b0), "r"(b1));
}

// ---------------------------------------------------------------------------
// Kernel 1: BN + Dense(48->128)+swish + Dense(128->128)+swish -> bf16 hi/lo
// Block: 64 rows, 256 threads.
// ---------------------------------------------------------------------------
__global__ __launch_bounds__(256)
void k_mlp(const float* __restrict__ x, const float* __restrict__ c,
           const float* __restrict__ bn_scale, const float* __restrict__ bn_bias,
           const float* __restrict__ bn_mean, const float* __restrict__ bn_var,
           const float* __restrict__ W0, const float* __restrict__ b0,
           const float* __restrict__ W1, const float* __restrict__ b1,
           float* __restrict__ out, int N)
{
    extern __shared__ float sm[];
    float* W0s = sm;
    float* W1s = W0s + 48 * 128;
    float* b0s = W1s + 128 * 128;
    float* b1s = b0s + 128;
    float* ab  = b1s + 128;
    float* A0s = ab + 96;
    float* A1s = A0s + 48 * 65;
    float* A2s = A1s + 128 * 65;

    const int tid  = threadIdx.x;
    const int row0 = blockIdx.x * 64;

    for (int i = tid; i < 48 * 128; i += 256)  W0s[i] = W0[i];
    for (int i = tid; i < 128 * 128; i += 256) W1s[i] = W1[i];
    if (tid < 128) { b0s[tid] = b0[tid]; b1s[tid] = b1[tid]; }
    if (tid < 48) {
        float a = bn_scale[tid] * rsqrtf(bn_var[tid] + 1e-5f);
        ab[tid]      = a;
        ab[48 + tid] = bn_bias[tid] - bn_mean[tid] * a;
    }
    __syncthreads();

    for (int idx = tid; idx < 64 * 32; idx += 256) {
        int k = idx & 31, r = idx >> 5;
        float v = x[(size_t)(row0 + r) * 64 + 32 + k];
        out[(size_t)(row0 + r) * 64 + 32 + k] = v;
        A0s[k * 65 + r] = v * ab[k] + ab[48 + k];
    }
    for (int idx = tid; idx < 64 * 16; idx += 256) {
        int k = idx & 15, r = idx >> 4;
        float v = c[(size_t)(row0 + r) * 16 + k];
        int kk = 32 + k;
        A0s[kk * 65 + r] = v * ab[kk] + ab[48 + kk];
    }
    __syncthreads();

    const int rt = tid >> 4, ct = tid & 15;
    const int r0 = rt * 4, f0 = ct * 8;

    {
        float acc[4][8];
        #pragma unroll
        for (int i = 0; i < 4; i++)
            #pragma unroll
            for (int q = 0; q < 8; q++) acc[i][q] = 0.0f;
        #pragma unroll 4
        for (int k = 0; k < 48; k++) {
            float a0 = A0s[k * 65 + r0 + 0];
            float a1 = A0s[k * 65 + r0 + 1];
            float a2 = A0s[k * 65 + r0 + 2];
            float a3 = A0s[k * 65 + r0 + 3];
            float4 wA = *(const float4*)&W0s[k * 128 + f0];
            float4 wB = *(const float4*)&W0s[k * 128 + f0 + 4];
            float w[8] = {wA.x, wA.y, wA.z, wA.w, wB.x, wB.y, wB.z, wB.w};
            #pragma unroll
            for (int q = 0; q < 8; q++) {
                acc[0][q] += a0 * w[q]; acc[1][q] += a1 * w[q];
                acc[2][q] += a2 * w[q]; acc[3][q] += a3 * w[q];
            }
        }
        #pragma unroll
        for (int q = 0; q < 8; q++) {
            float bb = b0s[f0 + q];
            #pragma unroll
            for (int i = 0; i < 4; i++)
                A1s[(f0 + q) * 65 + (r0 + i)] = swishf(acc[i][q] + bb);
        }
    }
    __syncthreads();

    {
        float acc[4][8];
        #pragma unroll
        for (int i = 0; i < 4; i++)
            #pragma unroll
            for (int q = 0; q < 8; q++) acc[i][q] = 0.0f;
        #pragma unroll 4
        for (int k = 0; k < 128; k++) {
            float a0 = A1s[k * 65 + r0 + 0];
            float a1 = A1s[k * 65 + r0 + 1];
            float a2 = A1s[k * 65 + r0 + 2];
            float a3 = A1s[k * 65 + r0 + 3];
            float4 wA = *(const float4*)&W1s[k * 128 + f0];
            float4 wB = *(const float4*)&W1s[k * 128 + f0 + 4];
            float w[8] = {wA.x, wA.y, wA.z, wA.w, wB.x, wB.y, wB.z, wB.w};
            #pragma unroll
            for (int q = 0; q < 8; q++) {
                acc[0][q] += a0 * w[q]; acc[1][q] += a1 * w[q];
                acc[2][q] += a2 * w[q]; acc[3][q] += a3 * w[q];
            }
        }
        #pragma unroll
        for (int q = 0; q < 8; q++) {
            float bb = b1s[f0 + q];
            #pragma unroll
            for (int i = 0; i < 4; i++)
                A2s[(f0 + q) * 64 + (r0 + i)] = swishf(acc[i][q] + bb);
        }
    }
    __syncthreads();

    for (int idx = tid; idx < 128 * 64; idx += 256) {
        int f = idx >> 6, r = idx & 63;
        float v = A2s[idx];
        __nv_bfloat16 h, l;
        split_bf16(v, &h, &l);
        g_h2_hi[(size_t)f * N + row0 + r] = h;
        g_h2_lo[(size_t)f * N + row0 + r] = l;
    }
}

// ---------------------------------------------------------------------------
// Kernel 2: bf16-split HMMA GEMM (per dim: 128m x 64n x 128k, 3 split terms)
// + per-row RQS spline. Block = 128 rows, 256 threads (8 warps x 16 rows).
// ---------------------------------------------------------------------------
#define SA 136              // smem stride in halves (conflict-free fragment LDS)
#define P_STRIDE 66

__global__ __launch_bounds__(256)
void k_spline_mma(const float* __restrict__ x, const float* __restrict__ W2,
                  const float* __restrict__ b2, float* __restrict__ out, int N)
{
    extern __shared__ char smem[];
    __nv_bfloat16* AH = (__nv_bfloat16*)smem;            // 128 x SA
    __nv_bfloat16* AL = AH + 128 * SA;                   // 128 x SA
    __nv_bfloat16* BH = AL + 128 * SA;                   // 64 x SA (n-major)
    __nv_bfloat16* BL = BH + 64 * SA;                    // 64 x SA
    float* P    = (float*)(BL + 64 * SA);                // 128 x 66
    float* bias = P + 128 * P_STRIDE;                    // 64

    const int tid  = threadIdx.x;
    const int warp = tid >> 5;
    const int lane = tid & 31;
    const int g    = lane >> 2;        // 0..7
    const int c2   = lane & 3;         // 0..3
    const int r0   = warp * 16;
    const int row0 = blockIdx.x * 128;

    // ---- Load A tile (h2 hi/lo), row-major [r][k]
    for (int idx = tid; idx < 128 * 128; idx += 256) {
        int k = idx >> 7, r = idx & 127;
        size_t gaddr = (size_t)k * N + row0 + r;
        AH[r * SA + k] = g_h2_hi[gaddr];
        AL[r * SA + k] = g_h2_lo[gaddr];
    }

    float logdet = 0.0f;
    const size_t grow = (size_t)(row0 + tid);   // valid for tid < 128

    for (int j = 0; j < 32; j++) {
        // ---- Load B chunk: W2[:, 47j .. 47j+46], transposed n-major, hi/lo
        for (int idx = tid; idx < 64 * 128; idx += 256) {
            int n = idx & 63, k = idx >> 6;
            float v = (n < 47) ? W2[(size_t)k * 1504 + j * 47 + n] : 0.0f;
            __nv_bfloat16 h, l;
            split_bf16(v, &h, &l);
            BH[n * SA + k] = h;
            BL[n * SA + k] = l;
        }
        if (tid < 64)
            bias[tid] = (tid < 47) ? b2[j * 47 + tid] : 0.0f;
        __syncthreads();

        // ---- GEMM: acc[t] covers rows {r0+g, r0+g+8}, cols {8t+2c2, +1}
        float acc[8][4];
        #pragma unroll
        for (int t = 0; t < 8; t++)
            #pragma unroll
            for (int q = 0; q < 4; q++) acc[t][q] = 0.0f;

        #pragma unroll
        for (int ks = 0; ks < 8; ks++) {
            const int ka = ks * 16 + 2 * c2;
            uint32_t ah0 = *(const uint32_t*)&AH[(r0 + g) * SA + ka];
            uint32_t ah1 = *(const uint32_t*)&AH[(r0 + g + 8) * SA + ka];
            uint32_t ah2 = *(const uint32_t*)&AH[(r0 + g) * SA + ka + 8];
            uint32_t ah3 = *(const uint32_t*)&AH[(r0 + g + 8) * SA + ka + 8];
            uint32_t al0 = *(const uint32_t*)&AL[(r0 + g) * SA + ka];
            uint32_t al1 = *(const uint32_t*)&AL[(r0 + g + 8) * SA + ka];
            uint32_t al2 = *(const uint32_t*)&AL[(r0 + g) * SA + ka + 8];
            uint32_t al3 = *(const uint32_t*)&AL[(r0 + g + 8) * SA + ka + 8];
            #pragma unroll
            for (int t = 0; t < 8; t++) {
                uint32_t bh0 = *(const uint32_t*)&BH[(8 * t + g) * SA + ka];
                uint32_t bh1 = *(const uint32_t*)&BH[(8 * t + g) * SA + ka + 8];
                mma16816(acc[t], ah0, ah1, ah2, ah3, bh0, bh1);   // hi*hi
                mma16816(acc[t], al0, al1, al2, al3, bh0, bh1);   // lo*hi
                uint32_t bl0 = *(const uint32_t*)&BL[(8 * t + g) * SA + ka];
                uint32_t bl1 = *(const uint32_t*)&BL[(8 * t + g) * SA + ka + 8];
                mma16816(acc[t], ah0, ah1, ah2, ah3, bl0, bl1);   // hi*lo
            }
        }

        // ---- Epilogue: bias, exp for softmax cols (<32), store to P
        #pragma unroll
        for (int t = 0; t < 8; t++) {
            int cb = 8 * t + 2 * c2;
            float bb0 = bias[cb], bb1 = bias[cb + 1];
            float v00 = acc[t][0] + bb0, v01 = acc[t][1] + bb1;
            float v10 = acc[t][2] + bb0, v11 = acc[t][3] + bb1;
            if (t < 4) {
                v00 = __expf(v00); v01 = __expf(v01);
                v10 = __expf(v10); v11 = __expf(v11);
            }
            *(float2*)&P[(r0 + g) * P_STRIDE + cb]     = make_float2(v00, v01);
            *(float2*)&P[(r0 + g + 8) * P_STRIDE + cb] = make_float2(v10, v11);
        }
        __syncthreads();

        // ---- Spline: one thread per row (validated round-1 math)
        if (tid < 128) {
            const float* pr = &P[tid * P_STRIDE];
            float tin = __ldg(&x[grow * 64 + j]);

            float sW = 0.0f, sH = 0.0f;
            #pragma unroll
            for (int i = 0; i < 16; i++) { sW += pr[i]; sH += pr[16 + i]; }
            float invW = __fdividef(1.0f, sW);
            float invH = __fdividef(1.0f, sH);

            float tc  = fminf(fmaxf(tin, 0.0f), 1.0f);
            bool  inb = (tin >= 0.0f) && (tin <= 1.0f);

            float xk = 0.0f, cy = 0.0f;
            float xk_b = 0.0f, yk_b = 0.0f;
            float dx_b = pr[0] * invW, dy_b = pr[16] * invH;
            int bidx = 0;
            #pragma unroll
            for (int i = 0; i < 16; i++) {
                float dxi = pr[i] * invW;
                float dyi = pr[16 + i] * invH;
                if (xk <= tc) { bidx = i; xk_b = xk; dx_b = dxi; yk_b = cy; dy_b = dyi; }
                xk += dxi; cy += dyi;
            }

            float v0 = pr[32 + ((bidx > 0) ? bidx - 1 : 0)];
            float v1 = pr[32 + ((bidx < 15) ? bidx : 14)];
            float sp0 = fmaxf(v0, 0.0f) + __logf(1.0f + __expf(-fabsf(v0)));
            float sp1 = fmaxf(v1, 0.0f) + __logf(1.0f + __expf(-fabsf(v1)));
            float d0 = (bidx == 0)  ? 1.0f : sp0;
            float d1 = (bidx == 15) ? 1.0f : sp1;

            float xi   = __fdividef(tc - xk_b, dx_b);
            float s    = __fdividef(dy_b, dx_b);
            float xi1m = xi * (1.0f - xi);
            float den  = s + (d0 + d1 - 2.0f * s) * xi1m;
            float num  = s * xi * xi + d0 * xi1m;
            float y_in = yk_b + dy_b * __fdividef(num, den);
            float omxi = 1.0f - xi;
            float dnum = d1 * xi * xi + 2.0f * s * xi1m + d0 * omxi * omxi;
            float dydx = __fdividef(s * s * dnum, den * den);

            out[grow * 64 + j] = inb ? y_in : tin;
            logdet += inb ? __logf(dydx) : 0.0f;
        }
        // next-iteration __syncthreads (after B load) orders spline P-reads
        // before the next P store; B/P buffers are disjoint.
    }

    if (tid < 128)
        out[(size_t)N * 64 + row0 + tid] = logdet;
}

// ---------------------------------------------------------------------------
extern "C" void kernel_launch(void* const* d_in, const int* in_sizes, int n_in,
                              void* d_out, int out_size)
{
    const float* x  = (const float*)d_in[0];
    const float* c  = (const float*)d_in[1];
    const float* bs = (const float*)d_in[2];
    const float* bb = (const float*)d_in[3];
    const float* bm = (const float*)d_in[4];
    const float* bv = (const float*)d_in[5];
    const float* W0 = (const float*)d_in[6];
    const float* b0 = (const float*)d_in[7];
    const float* W1 = (const float*)d_in[8];
    const float* b1 = (const float*)d_in[9];
    const float* W2 = (const float*)d_in[10];
    const float* b2 = (const float*)d_in[11];
    float* out = (float*)d_out;

    int N = in_sizes[0] / 64;

    size_t sm1 = (size_t)(48*128 + 128*128 + 128 + 128 + 96 + 48*65 + 128*65 + 128*64) * sizeof(float);
    // A: 2*128*SA halves, B: 2*64*SA halves, P: 128*66 f32, bias: 64 f32
    size_t sm2 = (size_t)(2 * 128 * SA + 2 * 64 * SA) * sizeof(__nv_bfloat16)
               + (size_t)(128 * P_STRIDE + 64) * sizeof(float);

    cudaFuncSetAttribute(k_mlp,        cudaFuncAttributeMaxDynamicSharedMemorySize, (int)sm1);
    cudaFuncSetAttribute(k_spline_mma, cudaFuncAttributeMaxDynamicSharedMemorySize, (int)sm2);

    k_mlp<<<N / 64, 256, sm1>>>(x, c, bs, bb, bm, bv, W0, b0, W1, b1, out, N);
    k_spline_mma<<<N / 128, 256, sm2>>>(x, W2, b2, out, N);
}

// round 4
// speedup vs baseline: 1.7016x; 1.4862x over previous
#include <cuda_runtime.h>
#include <cuda_bf16.h>
#include <math.h>
#include <stdint.h>

#define NMAX 65536
#define SA 136               // smem/tile stride in halves (conflict-free frag LDS)
#define P_STRIDE 66
#define BHALF (64 * SA)      // 8704 halves per split per dim-tile
#define BBUF (2 * BHALF)     // hi+lo, 17408 halves = 34816 bytes per j

// h2 scratch as bf16 hi/lo splits, transposed: [f * N + row]
__device__ __nv_bfloat16 g_h2_hi[128 * NMAX];
__device__ __nv_bfloat16 g_h2_lo[128 * NMAX];
// Pre-split W2 tiles: per j (32), [hi: 64xSA][lo: 64xSA], n-major, zero-padded
__device__ __nv_bfloat16 g_w2s[32 * BBUF];
// Padded bias: [32][64]
__device__ float g_b2p[32 * 64];

__device__ __forceinline__ float swishf(float v) {
    return __fdividef(v, 1.0f + __expf(-v));
}

__device__ __forceinline__ void split_bf16(float v, __nv_bfloat16* h, __nv_bfloat16* l) {
    __nv_bfloat16 hh = __float2bfloat16(v);
    *h = hh;
    *l = __float2bfloat16(v - __bfloat162float(hh));
}

__device__ __forceinline__ void mma16816(float* c,
                                         uint32_t a0, uint32_t a1, uint32_t a2, uint32_t a3,
                                         uint32_t b0, uint32_t b1) {
    asm volatile(
        "mma.sync.aligned.m16n8k16.row.col.f32.bf16.bf16.f32 "
        "{%0,%1,%2,%3}, {%4,%5,%6,%7}, {%8,%9}, {%0,%1,%2,%3};"
        : "+f"(c[0]), "+f"(c[1]), "+f"(c[2]), "+f"(c[3])
        : "r"(a0), "r"(a1), "r"(a2), "r"(a3), "r"(b0), "r"(b1));
}

__device__ __forceinline__ uint32_t smem_u32(const void* p) {
    uint32_t a;
    asm("{ .reg .u64 t; cvta.to.shared.u64 t, %1; cvt.u32.u64 %0, t; }" : "=r"(a) : "l"(p));
    return a;
}

// ---------------------------------------------------------------------------
// Prep: split W2 into bf16 hi/lo tiles (n-major, padded) + padded bias
// ---------------------------------------------------------------------------
__global__ __launch_bounds__(256)
void k_prep(const float* __restrict__ W2, const float* __restrict__ b2)
{
    int idx = blockIdx.x * 256 + threadIdx.x;
    if (idx < 32 * BHALF) {
        int j = idx / BHALF;
        int rem = idx - j * BHALF;
        int n = rem / SA;
        int k = rem - n * SA;
        float v = (n < 47 && k < 128) ? W2[(size_t)k * 1504 + j * 47 + n] : 0.0f;
        __nv_bfloat16 h, l;
        split_bf16(v, &h, &l);
        g_w2s[(size_t)j * BBUF + rem]          = h;
        g_w2s[(size_t)j * BBUF + BHALF + rem]  = l;
    }
    if (idx < 32 * 64) {
        int j = idx >> 6, cc = idx & 63;
        g_b2p[idx] = (cc < 47) ? b2[j * 47 + cc] : 0.0f;
    }
}

// ---------------------------------------------------------------------------
// Kernel 1: BN + Dense(48->128)+swish + Dense(128->128)+swish -> bf16 hi/lo
// ---------------------------------------------------------------------------
__global__ __launch_bounds__(256)
void k_mlp(const float* __restrict__ x, const float* __restrict__ c,
           const float* __restrict__ bn_scale, const float* __restrict__ bn_bias,
           const float* __restrict__ bn_mean, const float* __restrict__ bn_var,
           const float* __restrict__ W0, const float* __restrict__ b0,
           const float* __restrict__ W1, const float* __restrict__ b1,
           float* __restrict__ out, int N)
{
    extern __shared__ float sm[];
    float* W0s = sm;
    float* W1s = W0s + 48 * 128;
    float* b0s = W1s + 128 * 128;
    float* b1s = b0s + 128;
    float* ab  = b1s + 128;
    float* A0s = ab + 96;
    float* A1s = A0s + 48 * 65;
    float* A2s = A1s + 128 * 65;

    const int tid  = threadIdx.x;
    const int row0 = blockIdx.x * 64;

    for (int i = tid; i < 48 * 128; i += 256)  W0s[i] = W0[i];
    for (int i = tid; i < 128 * 128; i += 256) W1s[i] = W1[i];
    if (tid < 128) { b0s[tid] = b0[tid]; b1s[tid] = b1[tid]; }
    if (tid < 48) {
        float a = bn_scale[tid] * rsqrtf(bn_var[tid] + 1e-5f);
        ab[tid]      = a;
        ab[48 + tid] = bn_bias[tid] - bn_mean[tid] * a;
    }
    __syncthreads();

    for (int idx = tid; idx < 64 * 32; idx += 256) {
        int k = idx & 31, r = idx >> 5;
        float v = x[(size_t)(row0 + r) * 64 + 32 + k];
        out[(size_t)(row0 + r) * 64 + 32 + k] = v;
        A0s[k * 65 + r] = v * ab[k] + ab[48 + k];
    }
    for (int idx = tid; idx < 64 * 16; idx += 256) {
        int k = idx & 15, r = idx >> 4;
        float v = c[(size_t)(row0 + r) * 16 + k];
        int kk = 32 + k;
        A0s[kk * 65 + r] = v * ab[kk] + ab[48 + kk];
    }
    __syncthreads();

    const int rt = tid >> 4, ct = tid & 15;
    const int r0 = rt * 4, f0 = ct * 8;

    {
        float acc[4][8];
        #pragma unroll
        for (int i = 0; i < 4; i++)
            #pragma unroll
            for (int q = 0; q < 8; q++) acc[i][q] = 0.0f;
        #pragma unroll 4
        for (int k = 0; k < 48; k++) {
            float a0 = A0s[k * 65 + r0 + 0];
            float a1 = A0s[k * 65 + r0 + 1];
            float a2 = A0s[k * 65 + r0 + 2];
            float a3 = A0s[k * 65 + r0 + 3];
            float4 wA = *(const float4*)&W0s[k * 128 + f0];
            float4 wB = *(const float4*)&W0s[k * 128 + f0 + 4];
            float w[8] = {wA.x, wA.y, wA.z, wA.w, wB.x, wB.y, wB.z, wB.w};
            #pragma unroll
            for (int q = 0; q < 8; q++) {
                acc[0][q] += a0 * w[q]; acc[1][q] += a1 * w[q];
                acc[2][q] += a2 * w[q]; acc[3][q] += a3 * w[q];
            }
        }
        #pragma unroll
        for (int q = 0; q < 8; q++) {
            float bb = b0s[f0 + q];
            #pragma unroll
            for (int i = 0; i < 4; i++)
                A1s[(f0 + q) * 65 + (r0 + i)] = swishf(acc[i][q] + bb);
        }
    }
    __syncthreads();

    {
        float acc[4][8];
        #pragma unroll
        for (int i = 0; i < 4; i++)
            #pragma unroll
            for (int q = 0; q < 8; q++) acc[i][q] = 0.0f;
        #pragma unroll 4
        for (int k = 0; k < 128; k++) {
            float a0 = A1s[k * 65 + r0 + 0];
            float a1 = A1s[k * 65 + r0 + 1];
            float a2 = A1s[k * 65 + r0 + 2];
            float a3 = A1s[k * 65 + r0 + 3];
            float4 wA = *(const float4*)&W1s[k * 128 + f0];
            float4 wB = *(const float4*)&W1s[k * 128 + f0 + 4];
            float w[8] = {wA.x, wA.y, wA.z, wA.w, wB.x, wB.y, wB.z, wB.w};
            #pragma unroll
            for (int q = 0; q < 8; q++) {
                acc[0][q] += a0 * w[q]; acc[1][q] += a1 * w[q];
                acc[2][q] += a2 * w[q]; acc[3][q] += a3 * w[q];
            }
        }
        #pragma unroll
        for (int q = 0; q < 8; q++) {
            float bb = b1s[f0 + q];
            #pragma unroll
            for (int i = 0; i < 4; i++)
                A2s[(f0 + q) * 64 + (r0 + i)] = swishf(acc[i][q] + bb);
        }
    }
    __syncthreads();

    for (int idx = tid; idx < 128 * 64; idx += 256) {
        int f = idx >> 6, r = idx & 63;
        float v = A2s[idx];
        __nv_bfloat16 h, l;
        split_bf16(v, &h, &l);
        g_h2_hi[(size_t)f * N + row0 + r] = h;
        g_h2_lo[(size_t)f * N + row0 + r] = l;
    }
}

// ---------------------------------------------------------------------------
// Kernel 2: bf16-split HMMA GEMM + warp-local RQS spline.
// Block = 128 rows, 256 threads (8 warps x 16 rows). Double-buffered B via
// cp.async; only one block-wide sync per dim.
// ---------------------------------------------------------------------------
__global__ __launch_bounds__(256)
void k_spline_mma(const float* __restrict__ x, float* __restrict__ out, int N)
{
    extern __shared__ char smem[];
    __nv_bfloat16* AH = (__nv_bfloat16*)smem;            // 128 x SA
    __nv_bfloat16* AL = AH + 128 * SA;                   // 128 x SA
    __nv_bfloat16* B0 = AL + 128 * SA;                   // 2 x BBUF (double buf)
    float* P    = (float*)(B0 + 2 * BBUF);               // 128 x 66
    float* bias = P + 128 * P_STRIDE;                    // 32 x 64

    const int tid  = threadIdx.x;
    const int warp = tid >> 5;
    const int lane = tid & 31;
    const int g    = lane >> 2;        // 0..7
    const int c2   = lane & 3;         // 0..3
    const int r0   = warp * 16;
    const int row0 = blockIdx.x * 128;

    // ---- Load A tile (h2 hi/lo), row-major [r][k]
    for (int idx = tid; idx < 128 * 128; idx += 256) {
        int k = idx >> 7, r = idx & 127;
        size_t gaddr = (size_t)k * N + row0 + r;
        AH[r * SA + k] = g_h2_hi[gaddr];
        AL[r * SA + k] = g_h2_lo[gaddr];
    }
    // ---- Bias table (all 32 dims)
    for (int idx = tid; idx < 32 * 64; idx += 256)
        bias[idx] = g_b2p[idx];

    // ---- Prefetch B(0) via cp.async (2176 x 16B chunks)
    {
        uint32_t bdst = smem_u32(B0);
        const char* bsrc = (const char*)g_w2s;
        #pragma unroll
        for (int it = 0; it < 9; it++) {
            int ch = tid + it * 256;
            if (ch < 2176) {
                asm volatile("cp.async.cg.shared.global [%0], [%1], 16;"
                             :: "r"(bdst + ch * 16), "l"(bsrc + ch * 16) : "memory");
            }
        }
        asm volatile("cp.async.commit_group;" ::: "memory");
    }

    float logdet = 0.0f;
    const int myrow = r0 + lane;                       // spline row (lane < 16)
    const size_t grow = (size_t)(row0 + myrow);

    for (int j = 0; j < 32; j++) {
        asm volatile("cp.async.wait_group 0;" ::: "memory");
        __syncthreads();    // B(j) visible to all; also orders A-load on j==0

        const __nv_bfloat16* BH = B0 + (j & 1) * BBUF;
        const __nv_bfloat16* BL = BH + BHALF;

        // ---- Prefetch B(j+1) into the other buffer
        if (j + 1 < 32) {
            uint32_t bdst = smem_u32(B0 + ((j + 1) & 1) * BBUF);
            const char* bsrc = (const char*)(g_w2s + (size_t)(j + 1) * BBUF);
            #pragma unroll
            for (int it = 0; it < 9; it++) {
                int ch = tid + it * 256;
                if (ch < 2176) {
                    asm volatile("cp.async.cg.shared.global [%0], [%1], 16;"
                                 :: "r"(bdst + ch * 16), "l"(bsrc + ch * 16) : "memory");
                }
            }
        }
        asm volatile("cp.async.commit_group;" ::: "memory");

        // ---- GEMM: warp computes rows r0..r0+15, cols 0..63 (3 split terms)
        float acc[8][4];
        #pragma unroll
        for (int t = 0; t < 8; t++)
            #pragma unroll
            for (int q = 0; q < 4; q++) acc[t][q] = 0.0f;

        #pragma unroll
        for (int ks = 0; ks < 8; ks++) {
            const int ka = ks * 16 + 2 * c2;
            uint32_t ah0 = *(const uint32_t*)&AH[(r0 + g) * SA + ka];
            uint32_t ah1 = *(const uint32_t*)&AH[(r0 + g + 8) * SA + ka];
            uint32_t ah2 = *(const uint32_t*)&AH[(r0 + g) * SA + ka + 8];
            uint32_t ah3 = *(const uint32_t*)&AH[(r0 + g + 8) * SA + ka + 8];
            uint32_t al0 = *(const uint32_t*)&AL[(r0 + g) * SA + ka];
            uint32_t al1 = *(const uint32_t*)&AL[(r0 + g + 8) * SA + ka];
            uint32_t al2 = *(const uint32_t*)&AL[(r0 + g) * SA + ka + 8];
            uint32_t al3 = *(const uint32_t*)&AL[(r0 + g + 8) * SA + ka + 8];
            #pragma unroll
            for (int t = 0; t < 8; t++) {
                uint32_t bh0 = *(const uint32_t*)&BH[(8 * t + g) * SA + ka];
                uint32_t bh1 = *(const uint32_t*)&BH[(8 * t + g) * SA + ka + 8];
                mma16816(acc[t], ah0, ah1, ah2, ah3, bh0, bh1);   // hi*hi
                mma16816(acc[t], al0, al1, al2, al3, bh0, bh1);   // lo*hi
                uint32_t bl0 = *(const uint32_t*)&BL[(8 * t + g) * SA + ka];
                uint32_t bl1 = *(const uint32_t*)&BL[(8 * t + g) * SA + ka + 8];
                mma16816(acc[t], ah0, ah1, ah2, ah3, bl0, bl1);   // hi*lo
            }
        }

        // ---- Epilogue: bias, exp for softmax cols (<32), store to warp-private P
        const float* bj = &bias[j * 64];
        #pragma unroll
        for (int t = 0; t < 8; t++) {
            int cb = 8 * t + 2 * c2;
            float2 bb = *(const float2*)&bj[cb];
            float v00 = acc[t][0] + bb.x, v01 = acc[t][1] + bb.y;
            float v10 = acc[t][2] + bb.x, v11 = acc[t][3] + bb.y;
            if (t < 4) {
                v00 = __expf(v00); v01 = __expf(v01);
                v10 = __expf(v10); v11 = __expf(v11);
            }
            *(float2*)&P[(r0 + g) * P_STRIDE + cb]     = make_float2(v00, v01);
            *(float2*)&P[(r0 + g + 8) * P_STRIDE + cb] = make_float2(v10, v11);
        }
        __syncwarp();

        // ---- Spline: warp-local, lanes 0..15 (one per row)
        if (lane < 16) {
            const float* pr = &P[myrow * P_STRIDE];
            float tin = __ldg(&x[grow * 64 + j]);

            float sW = 0.0f, sH = 0.0f;
            #pragma unroll
            for (int i = 0; i < 16; i++) { sW += pr[i]; sH += pr[16 + i]; }
            float invW = __fdividef(1.0f, sW);
            float invH = __fdividef(1.0f, sH);

            float tc  = fminf(fmaxf(tin, 0.0f), 1.0f);
            bool  inb = (tin >= 0.0f) && (tin <= 1.0f);

            float xk = 0.0f, cy = 0.0f;
            float xk_b = 0.0f, yk_b = 0.0f;
            float dx_b = pr[0] * invW, dy_b = pr[16] * invH;
            int bidx = 0;
            #pragma unroll
            for (int i = 0; i < 16; i++) {
                float dxi = pr[i] * invW;
                float dyi = pr[16 + i] * invH;
                if (xk <= tc) { bidx = i; xk_b = xk; dx_b = dxi; yk_b = cy; dy_b = dyi; }
                xk += dxi; cy += dyi;
            }

            float v0 = pr[32 + ((bidx > 0) ? bidx - 1 : 0)];
            float v1 = pr[32 + ((bidx < 15) ? bidx : 14)];
            float sp0 = fmaxf(v0, 0.0f) + __logf(1.0f + __expf(-fabsf(v0)));
            float sp1 = fmaxf(v1, 0.0f) + __logf(1.0f + __expf(-fabsf(v1)));
            float d0 = (bidx == 0)  ? 1.0f : sp0;
            float d1 = (bidx == 15) ? 1.0f : sp1;

            float xi   = __fdividef(tc - xk_b, dx_b);
            float s    = __fdividef(dy_b, dx_b);
            float xi1m = xi * (1.0f - xi);
            float den  = s + (d0 + d1 - 2.0f * s) * xi1m;
            float num  = s * xi * xi + d0 * xi1m;
            float y_in = yk_b + dy_b * __fdividef(num, den);
            float omxi = 1.0f - xi;
            float dnum = d1 * xi * xi + 2.0f * s * xi1m + d0 * omxi * omxi;
            float dydx = __fdividef(s * s * dnum, den * den);

            out[grow * 64 + j] = inb ? y_in : tin;
            logdet += inb ? __logf(dydx) : 0.0f;
        }
        __syncwarp();   // P reads done before next iteration's epilogue writes
    }

    if (lane < 16)
        out[(size_t)N * 64 + row0 + myrow] = logdet;
}

// ---------------------------------------------------------------------------
extern "C" void kernel_launch(void* const* d_in, const int* in_sizes, int n_in,
                              void* d_out, int out_size)
{
    const float* x  = (const float*)d_in[0];
    const float* c  = (const float*)d_in[1];
    const float* bs = (const float*)d_in[2];
    const float* bb = (const float*)d_in[3];
    const float* bm = (const float*)d_in[4];
    const float* bv = (const float*)d_in[5];
    const float* W0 = (const float*)d_in[6];
    const float* b0 = (const float*)d_in[7];
    const float* W1 = (const float*)d_in[8];
    const float* b1 = (const float*)d_in[9];
    const float* W2 = (const float*)d_in[10];
    const float* b2 = (const float*)d_in[11];
    float* out = (float*)d_out;

    int N = in_sizes[0] / 64;

    size_t sm1 = (size_t)(48*128 + 128*128 + 128 + 128 + 96 + 48*65 + 128*65 + 128*64) * sizeof(float);
    // A: 2*128*SA halves; B: 2*BBUF halves; P: 128*66 f32; bias: 32*64 f32
    size_t sm2 = (size_t)(2 * 128 * SA + 2 * BBUF) * sizeof(__nv_bfloat16)
               + (size_t)(128 * P_STRIDE + 32 * 64) * sizeof(float);

    cudaFuncSetAttribute(k_mlp,        cudaFuncAttributeMaxDynamicSharedMemorySize, (int)sm1);
    cudaFuncSetAttribute(k_spline_mma, cudaFuncAttributeMaxDynamicSharedMemorySize, (int)sm2);

    k_prep<<<(32 * BHALF + 255) / 256, 256>>>(W2, b2);
    k_mlp<<<N / 64, 256, sm1>>>(x, c, bs, bb, bm, bv, W0, b0, W1, b1, out, N);
    k_spline_mma<<<N / 128, 256, sm2>>>(x, out, N);
}